// round 1
// baseline (speedup 1.0000x reference)
#include <cuda_runtime.h>
#include <cuda_bf16.h>
#include <math.h>

// ---------------- problem constants ----------------
#define BSZ   32
#define HH    56
#define WW_   56
#define CC    192
#define LL    (HH*WW_)          // 3136
#define WS    7
#define NN    49                // ws*ws
#define NHH   6
#define HD    32                // C/nh
#define SHIFT 3
#define NWIN  64                // (56/7)^2 windows per image
#define BW    (BSZ*NWIN)        // 2048
#define TOK   (BW*NN)           // 100352 window-space tokens (== B*L)
#define HID   768

// ---------------- scratch (static device, no allocs) ----------------
__device__ float g_win [(size_t)TOK*CC];    // LN1+roll+partition out; reused for proj out
__device__ float g_qkv [(size_t)TOK*3*CC];
__device__ float g_attn[(size_t)TOK*CC];    // attn out; reused for LN2 out
__device__ float g_x1  [(size_t)TOK*CC];    // residual 1
__device__ float g_h1  [(size_t)TOK*HID];   // fc1+gelu out

// ---------------- helpers ----------------
__device__ __forceinline__ float warpSum(float v){
    #pragma unroll
    for (int o=16;o;o>>=1) v += __shfl_xor_sync(0xffffffffu, v, o);
    return v;
}
__device__ __forceinline__ float warpMax(float v){
    #pragma unroll
    for (int o=16;o;o>>=1) v = fmaxf(v, __shfl_xor_sync(0xffffffffu, v, o));
    return v;
}

// ---------------- LayerNorm (192 ch), optionally gathering through roll+window partition ----------------
template<bool GATHER>
__global__ __launch_bounds__(192) void ln_kernel(const float* __restrict__ x,
                                                 const float* __restrict__ gamma,
                                                 const float* __restrict__ beta,
                                                 float* __restrict__ out)
{
    int t = blockIdx.x;          // window-space token (GATHER) or plain row
    int tid = threadIdx.x;
    size_t src;
    if (GATHER) {
        int win = t / NN, n = t % NN;
        int b = win / NWIN, wi = win % NWIN;
        int wh = wi >> 3, ww = wi & 7;
        int r = n / WS, c = n % WS;
        int hr = wh*WS + r, wr = ww*WS + c;
        int h = hr + SHIFT; if (h >= HH) h -= HH;
        int w = wr + SHIFT; if (w >= WW_) w -= WW_;
        src = ((size_t)b*LL + h*WW_ + w) * CC + tid;
    } else {
        src = (size_t)t * CC + tid;
    }
    float v = x[src];

    __shared__ float red[8];
    int lane = tid & 31, wid = tid >> 5;
    float s = warpSum(v);
    if (lane == 0) red[wid] = s;
    __syncthreads();
    if (tid == 0) {
        float m = 0.f;
        #pragma unroll
        for (int i=0;i<6;i++) m += red[i];
        red[6] = m * (1.f/CC);
    }
    __syncthreads();
    float mean = red[6];
    float d = v - mean;
    s = warpSum(d*d);
    __syncthreads();
    if (lane == 0) red[wid] = s;
    __syncthreads();
    if (tid == 0) {
        float q = 0.f;
        #pragma unroll
        for (int i=0;i<6;i++) q += red[i];
        red[7] = rsqrtf(q * (1.f/CC) + 1e-5f);
    }
    __syncthreads();
    float rstd = red[7];
    out[(size_t)t*CC + tid] = d * rstd * gamma[tid] + beta[tid];
}

// ---------------- tiled fp32 GEMM: out[m][n] = sum_k A[m][k]*W[n][k] + bias[n] (+epi) ----------------
// EPI: 0 = bias only, 1 = bias + exact gelu, 2 = bias + addsrc
template<int EPI>
__global__ __launch_bounds__(256) void gemm_nt(const float* __restrict__ A,
                                               const float* __restrict__ W,
                                               const float* __restrict__ bias,
                                               const float* __restrict__ addsrc,
                                               float* __restrict__ out,
                                               int M, int N, int K)
{
    constexpr int BM = 128, BN = 64, BK = 16;
    __shared__ float As[BK][BM+4];
    __shared__ float Bs[BK][BN+4];

    int tid = threadIdx.x;
    int tx = tid & 15, ty = tid >> 4;
    int mBase = blockIdx.y * BM, nBase = blockIdx.x * BN;

    const float* Aptr = A + (size_t)mBase * K;
    const float* Wptr = W + (size_t)nBase * K;

    float acc[8][4];
    #pragma unroll
    for (int r=0;r<8;r++)
        #pragma unroll
        for (int c=0;c<4;c++) acc[r][c] = 0.f;

    int arow = tid >> 2;       // 0..63
    int ak4  = tid & 3;        // 0..3 (float4 index within 16-wide k chunk)

    for (int kt = 0; kt < K; kt += BK) {
        #pragma unroll
        for (int u=0; u<2; u++) {
            int row = arow + u*64;
            float4 va = *(const float4*)(Aptr + (size_t)row*K + kt + ak4*4);
            As[ak4*4+0][row] = va.x;
            As[ak4*4+1][row] = va.y;
            As[ak4*4+2][row] = va.z;
            As[ak4*4+3][row] = va.w;
        }
        {
            float4 vb = *(const float4*)(Wptr + (size_t)arow*K + kt + ak4*4);
            Bs[ak4*4+0][arow] = vb.x;
            Bs[ak4*4+1][arow] = vb.y;
            Bs[ak4*4+2][arow] = vb.z;
            Bs[ak4*4+3][arow] = vb.w;
        }
        __syncthreads();

        #pragma unroll
        for (int kk=0; kk<BK; kk++) {
            float4 a0 = *(const float4*)&As[kk][ty*8];
            float4 a1 = *(const float4*)&As[kk][ty*8+4];
            float4 b0 = *(const float4*)&Bs[kk][tx*4];
            float ar[8] = {a0.x,a0.y,a0.z,a0.w,a1.x,a1.y,a1.z,a1.w};
            float bc[4] = {b0.x,b0.y,b0.z,b0.w};
            #pragma unroll
            for (int r=0;r<8;r++)
                #pragma unroll
                for (int c=0;c<4;c++)
                    acc[r][c] = fmaf(ar[r], bc[c], acc[r][c]);
        }
        __syncthreads();
    }

    float4 bb = *(const float4*)(bias + nBase + tx*4);
    float bv[4] = {bb.x, bb.y, bb.z, bb.w};
    #pragma unroll
    for (int r=0;r<8;r++) {
        size_t m = (size_t)(mBase + ty*8 + r);
        size_t o = m * N + nBase + tx*4;
        float4 v;
        float tmp[4];
        #pragma unroll
        for (int c=0;c<4;c++) {
            float u = acc[r][c] + bv[c];
            if (EPI == 1) u = 0.5f * u * (1.f + erff(u * 0.7071067811865476f));
            tmp[c] = u;
        }
        if (EPI == 2) {
            float4 ad = *(const float4*)(addsrc + o);
            tmp[0]+=ad.x; tmp[1]+=ad.y; tmp[2]+=ad.z; tmp[3]+=ad.w;
        }
        v.x=tmp[0]; v.y=tmp[1]; v.z=tmp[2]; v.w=tmp[3];
        *(float4*)(out + o) = v;
    }
}

// ---------------- windowed attention: one block per (window, head) ----------------
__global__ __launch_bounds__(128) void attn_kernel(const float* __restrict__ qkv,
                                                   const float* __restrict__ rpb,
                                                   float* __restrict__ out)
{
    int win  = blockIdx.x / NHH;
    int head = blockIdx.x % NHH;
    int tid  = threadIdx.x;
    int lane = tid & 31, w = tid >> 5;

    __shared__ float sq[NN*33], sk[NN*33], sv[NN*33];
    __shared__ float sp[NN*50];
    __shared__ int   sgrp[NN];

    const float* base = qkv + (size_t)win*NN*(3*CC) + head*HD;
    for (int i = tid; i < NN*HD; i += 128) {
        int n = i >> 5, d = i & 31;
        sq[n*33+d] = base[(size_t)n*(3*CC) + d];
        sk[n*33+d] = base[(size_t)n*(3*CC) + CC + d];
        sv[n*33+d] = base[(size_t)n*(3*CC) + 2*CC + d];
    }
    if (tid < NN) {
        int wi = win % NWIN;
        int wh = wi >> 3, ww = wi & 7;
        int r = tid / WS, c = tid % WS;
        int hh = wh*WS + r, wg = ww*WS + c;
        int gh = (hh < HH-WS) ? 0 : ((hh < HH-SHIFT) ? 1 : 2);
        int gw = (wg < WW_-WS) ? 0 : ((wg < WW_-SHIFT) ? 1 : 2);
        sgrp[tid] = gh*3 + gw;
    }
    __syncthreads();

    const float scale = 0.17677669529663687f; // 32^-0.5
    for (int i = w; i < NN; i += 4) {
        int ih = i / WS, iw = i % WS;
        int j1 = lane;
        int j2 = lane + 32;
        bool has2 = (j2 < NN);
        int j2c = has2 ? j2 : 0;
        float a1 = 0.f, a2 = 0.f;
        #pragma unroll
        for (int d = 0; d < HD; d++) {
            float qd = sq[i*33+d];
            a1 = fmaf(qd, sk[j1*33+d], a1);
            a2 = fmaf(qd, sk[j2c*33+d], a2);
        }
        // bias + mask for j1
        int jh = j1 / WS, jw = j1 % WS;
        int ridx = (ih - jh + 6)*13 + (iw - jw + 6);
        float s1 = a1*scale + rpb[ridx*NHH + head] + ((sgrp[i] != sgrp[j1]) ? -100.f : 0.f);
        float s2 = -1e30f;
        if (has2) {
            jh = j2 / WS; jw = j2 % WS;
            ridx = (ih - jh + 6)*13 + (iw - jw + 6);
            s2 = a2*scale + rpb[ridx*NHH + head] + ((sgrp[i] != sgrp[j2]) ? -100.f : 0.f);
        }
        float m = warpMax(fmaxf(s1, s2));
        float e1 = __expf(s1 - m);
        float e2 = has2 ? __expf(s2 - m) : 0.f;
        float sum = warpSum(e1 + e2);
        float inv = 1.f / sum;
        sp[i*50 + j1] = e1 * inv;
        if (has2) sp[i*50 + j2] = e2 * inv;
    }
    __syncwarp();

    for (int i = w; i < NN; i += 4) {
        int d = lane;
        float acc = 0.f;
        #pragma unroll 7
        for (int j = 0; j < NN; j++)
            acc = fmaf(sp[i*50+j], sv[j*33+d], acc);
        out[((size_t)(win*NN + i))*CC + head*HD + d] = acc;
    }
}

// ---------------- window reverse + un-roll + residual add ----------------
__global__ __launch_bounds__(256) void scatter_add_kernel(const float* __restrict__ x,
                                                          const float* __restrict__ proj,
                                                          float* __restrict__ x1)
{
    size_t idx = (size_t)blockIdx.x * blockDim.x + threadIdx.x;
    if (idx >= (size_t)TOK*CC) return;
    int c = (int)(idx % CC);
    size_t row = idx / CC;
    int l = (int)(row % LL);
    int b = (int)(row / LL);
    int h = l / WW_, wcol = l % WW_;
    int hr = h - SHIFT; if (hr < 0) hr += HH;
    int wr = wcol - SHIFT; if (wr < 0) wr += WW_;
    int t = (b*NWIN + (hr/WS)*8 + (wr/WS))*NN + (hr%WS)*WS + (wr%WS);
    x1[idx] = x[idx] + proj[(size_t)t*CC + c];
}

// ---------------- launch ----------------
extern "C" void kernel_launch(void* const* d_in, const int* in_sizes, int n_in,
                              void* d_out, int out_size)
{
    const float* x      = (const float*)d_in[0];
    const float* qkv_w  = (const float*)d_in[1];
    const float* qkv_b  = (const float*)d_in[2];
    const float* proj_w = (const float*)d_in[3];
    const float* proj_b = (const float*)d_in[4];
    const float* rpb    = (const float*)d_in[5];
    const float* n1g    = (const float*)d_in[6];
    const float* n1b    = (const float*)d_in[7];
    const float* n2g    = (const float*)d_in[8];
    const float* n2b    = (const float*)d_in[9];
    const float* w1     = (const float*)d_in[10];
    const float* b1     = (const float*)d_in[11];
    const float* w2     = (const float*)d_in[12];
    const float* b2     = (const float*)d_in[13];
    float* out = (float*)d_out;

    float *p_win, *p_qkv, *p_attn, *p_x1, *p_h1;
    cudaGetSymbolAddress((void**)&p_win,  g_win);
    cudaGetSymbolAddress((void**)&p_qkv,  g_qkv);
    cudaGetSymbolAddress((void**)&p_attn, g_attn);
    cudaGetSymbolAddress((void**)&p_x1,   g_x1);
    cudaGetSymbolAddress((void**)&p_h1,   g_h1);

    // 1) LN1 + roll + window partition  -> g_win (TOK x 192)
    ln_kernel<true><<<TOK, 192>>>(x, n1g, n1b, p_win);

    // 2) qkv GEMM: (TOK x 192) @ (576 x 192)^T -> g_qkv
    gemm_nt<0><<<dim3(3*CC/64, TOK/128), 256>>>(p_win, qkv_w, qkv_b, nullptr, p_qkv, TOK, 3*CC, CC);

    // 3) windowed attention -> g_attn (TOK x 192, head-interleaved)
    attn_kernel<<<BW*NHH, 128>>>(p_qkv, rpb, p_attn);

    // 4) proj GEMM -> g_win (reuse)
    gemm_nt<0><<<dim3(CC/64, TOK/128), 256>>>(p_attn, proj_w, proj_b, nullptr, p_win, TOK, CC, CC);

    // 5) window reverse + roll back + residual -> g_x1
    scatter_add_kernel<<<(unsigned)(((size_t)TOK*CC + 255)/256), 256>>>(x, p_win, p_x1);

    // 6) LN2 -> g_attn (reuse)
    ln_kernel<false><<<TOK, 192>>>(p_x1, n2g, n2b, p_attn);

    // 7) fc1 + gelu -> g_h1
    gemm_nt<1><<<dim3(HID/64, TOK/128), 256>>>(p_attn, w1, b1, nullptr, p_h1, TOK, HID, CC);

    // 8) fc2 + bias + residual -> d_out
    gemm_nt<2><<<dim3(CC/64, TOK/128), 256>>>(p_h1, w2, b2, p_x1, out, TOK, CC, HID);
}

// round 4
// speedup vs baseline: 2.3018x; 2.3018x over previous
#include <cuda_runtime.h>
#include <cuda_bf16.h>
#include <math.h>
#include <stdint.h>

// ---------------- problem constants ----------------
#define BSZ   32
#define HH    56
#define WW_   56
#define CC    192
#define LL    (HH*WW_)          // 3136
#define WS    7
#define NN    49
#define NHH   6
#define HD    32
#define SHIFT 3
#define NWIN  64
#define BW    (BSZ*NWIN)        // 2048
#define TOK   (BW*NN)           // 100352
#define HID   768

typedef __nv_bfloat16 bf16;

// ---------------- scratch (static device, no allocs) ----------------
__device__ __align__(256) bf16 g_ln1 [(size_t)TOK*CC];
__device__ __align__(256) bf16 g_qkvb[(size_t)TOK*3*CC];
__device__ __align__(256) bf16 g_attnb[(size_t)TOK*CC];
__device__ __align__(256) bf16 g_ln2 [(size_t)TOK*CC];
__device__ __align__(256) bf16 g_h1b [(size_t)TOK*HID];
__device__ __align__(256) float g_x1 [(size_t)TOK*CC];
__device__ __align__(256) bf16 g_wq[3*CC*CC];
__device__ __align__(256) bf16 g_wp[CC*CC];
__device__ __align__(256) bf16 g_w1[HID*CC];
__device__ __align__(256) bf16 g_w2[CC*HID];

// ---------------- helpers ----------------
__device__ __forceinline__ float warpSum(float v){
    #pragma unroll
    for (int o=16;o;o>>=1) v += __shfl_xor_sync(0xffffffffu, v, o);
    return v;
}
__device__ __forceinline__ float warpMax(float v){
    #pragma unroll
    for (int o=16;o;o>>=1) v = fmaxf(v, __shfl_xor_sync(0xffffffffu, v, o));
    return v;
}

static __device__ __forceinline__ size_t winrow_to_img(int m){
    // window-space token -> image-space flat row (b*L + h*W + w), incl. un-roll
    int win = m / NN, n = m % NN;
    int b = win >> 6, wi = win & 63;
    int hr = (wi >> 3)*WS + n/WS;
    int wr = (wi & 7)*WS + n%WS;
    int h = hr + SHIFT; if (h >= HH) h -= HH;
    int w = wr + SHIFT; if (w >= WW_) w -= WW_;
    return (size_t)b*LL + (size_t)h*WW_ + w;
}

// ---------------- fp32 -> bf16 convert ----------------
__global__ void f2bf_kernel(const float* __restrict__ s, bf16* __restrict__ d, int n){
    int i = blockIdx.x*256 + threadIdx.x;
    if (i < n) d[i] = __float2bfloat16(s[i]);
}

// ---------------- LayerNorm (192 ch) -> bf16, optional roll+window gather ----------------
template<bool GATHER>
__global__ __launch_bounds__(192) void ln_kernel(const float* __restrict__ x,
                                                 const float* __restrict__ gamma,
                                                 const float* __restrict__ beta,
                                                 bf16* __restrict__ out)
{
    int t = blockIdx.x;
    int tid = threadIdx.x;
    size_t src;
    if (GATHER) {
        src = winrow_to_img(t) * CC + tid;
    } else {
        src = (size_t)t * CC + tid;
    }
    float v = x[src];

    __shared__ float red[8];
    int lane = tid & 31, wid = tid >> 5;
    float s = warpSum(v);
    if (lane == 0) red[wid] = s;
    __syncthreads();
    if (tid == 0) {
        float m = 0.f;
        #pragma unroll
        for (int i=0;i<6;i++) m += red[i];
        red[6] = m * (1.f/CC);
    }
    __syncthreads();
    float mean = red[6];
    float d = v - mean;
    s = warpSum(d*d);
    __syncthreads();
    if (lane == 0) red[wid] = s;
    __syncthreads();
    if (tid == 0) {
        float q = 0.f;
        #pragma unroll
        for (int i=0;i<6;i++) q += red[i];
        red[7] = rsqrtf(q * (1.f/CC) + 1e-5f);
    }
    __syncthreads();
    float rstd = red[7];
    out[(size_t)t*CC + tid] = __float2bfloat16(d * rstd * gamma[tid] + beta[tid]);
}

// ---------------- HMMA bf16 GEMM: out[m][n] = sum_k A[m][k]*W[n][k] (+epi) ----------------
// tile 128(M) x 64(N), BK=32, 256 threads, warp grid 4(M) x 2(N), warp tile 32x32.
// mma.sync.aligned.m16n8k16.row.col.f32.bf16.bf16.f32
// EPI 0: +bias -> bf16  |  1: +bias,gelu -> bf16  |  2: +bias +x[imgrow] -> fp32  |  3: +bias +xin[row] -> fp32
#define LDA 40   // smem row stride in bf16 elems (80B = 20 banks -> conflict-free frags)

template<int EPI>
__global__ __launch_bounds__(256) void mma_gemm(const bf16* __restrict__ A,
                                                const bf16* __restrict__ Wt,
                                                const float* __restrict__ bias,
                                                const float* __restrict__ xin,
                                                void* __restrict__ outp,
                                                int N, int K)
{
    __shared__ __align__(16) bf16 As[128*LDA];
    __shared__ __align__(16) bf16 Bs[64*LDA];

    int tid = threadIdx.x;
    int wid = tid >> 5, lane = tid & 31;
    int g = lane >> 2, t4 = lane & 3;
    int wm = (wid >> 1) * 32;     // warp M offset in tile
    int wn = (wid & 1) * 32;      // warp N offset in tile
    int mBase = blockIdx.y * 128;
    int nBase = blockIdx.x * 64;

    const bf16* Abase = A  + (size_t)mBase * K;
    const bf16* Bbase = Wt + (size_t)nBase * K;

    float acc[2][4][4];
    #pragma unroll
    for (int mi=0;mi<2;mi++)
        #pragma unroll
        for (int ni=0;ni<4;ni++)
            #pragma unroll
            for (int c=0;c<4;c++) acc[mi][ni][c] = 0.f;

    for (int kt = 0; kt < K; kt += 32) {
        // load A tile: 128 x 32 bf16, 8 bf16 (uint4) per op, 2 per thread
        #pragma unroll
        for (int i = 0; i < 2; i++) {
            int idx = tid + i*256;
            int r = idx >> 2, c8 = idx & 3;
            uint4 v = *(const uint4*)(Abase + (size_t)r*K + kt + c8*8);
            *(uint4*)(&As[r*LDA + c8*8]) = v;
        }
        // load B tile: 64 x 32
        {
            int r = tid >> 2, c8 = tid & 3;
            uint4 v = *(const uint4*)(Bbase + (size_t)r*K + kt + c8*8);
            *(uint4*)(&Bs[r*LDA + c8*8]) = v;
        }
        __syncthreads();

        #pragma unroll
        for (int ks = 0; ks < 2; ks++) {
            uint32_t af[2][4], bfr[4][2];
            #pragma unroll
            for (int mi = 0; mi < 2; mi++) {
                int r0 = wm + mi*16 + g;
                af[mi][0] = *(const uint32_t*)&As[(r0  )*LDA + ks*16 + t4*2    ];
                af[mi][1] = *(const uint32_t*)&As[(r0+8)*LDA + ks*16 + t4*2    ];
                af[mi][2] = *(const uint32_t*)&As[(r0  )*LDA + ks*16 + t4*2 + 8];
                af[mi][3] = *(const uint32_t*)&As[(r0+8)*LDA + ks*16 + t4*2 + 8];
            }
            #pragma unroll
            for (int ni = 0; ni < 4; ni++) {
                int n0 = wn + ni*8 + g;
                bfr[ni][0] = *(const uint32_t*)&Bs[n0*LDA + ks*16 + t4*2    ];
                bfr[ni][1] = *(const uint32_t*)&Bs[n0*LDA + ks*16 + t4*2 + 8];
            }
            #pragma unroll
            for (int mi = 0; mi < 2; mi++)
                #pragma unroll
                for (int ni = 0; ni < 4; ni++) {
                    asm volatile(
                        "mma.sync.aligned.m16n8k16.row.col.f32.bf16.bf16.f32 "
                        "{%0,%1,%2,%3}, {%4,%5,%6,%7}, {%8,%9}, {%0,%1,%2,%3};"
                        : "+f"(acc[mi][ni][0]), "+f"(acc[mi][ni][1]),
                          "+f"(acc[mi][ni][2]), "+f"(acc[mi][ni][3])
                        : "r"(af[mi][0]), "r"(af[mi][1]), "r"(af[mi][2]), "r"(af[mi][3]),
                          "r"(bfr[ni][0]), "r"(bfr[ni][1]));
                }
        }
        __syncthreads();
    }

    // ---------------- epilogue ----------------
    #pragma unroll
    for (int ni = 0; ni < 4; ni++) {
        int n = nBase + wn + ni*8 + t4*2;
        float b0v = __ldg(bias + n), b1v = __ldg(bias + n + 1);
        #pragma unroll
        for (int mi = 0; mi < 2; mi++) {
            #pragma unroll
            for (int h = 0; h < 2; h++) {
                int m = mBase + wm + mi*16 + h*8 + g;
                float u0 = acc[mi][ni][h*2+0] + b0v;
                float u1 = acc[mi][ni][h*2+1] + b1v;
                if (EPI == 1) {
                    u0 = 0.5f * u0 * (1.f + erff(u0 * 0.7071067811865476f));
                    u1 = 0.5f * u1 * (1.f + erff(u1 * 0.7071067811865476f));
                }
                if (EPI == 0 || EPI == 1) {
                    __nv_bfloat162 p = __floats2bfloat162_rn(u0, u1);
                    *(uint32_t*)((bf16*)outp + (size_t)m * N + n) = *(uint32_t*)&p;
                } else {
                    size_t drow = (EPI == 2) ? winrow_to_img(m) : (size_t)m;
                    size_t o = drow * CC + n;
                    float2 xv = *(const float2*)(xin + o);
                    float2 ov; ov.x = u0 + xv.x; ov.y = u1 + xv.y;
                    *(float2*)((float*)outp + o) = ov;
                }
            }
        }
    }
}

// ---------------- windowed attention: one block per (window, head), bf16 in/out ----------------
__global__ __launch_bounds__(128) void attn_kernel(const bf16* __restrict__ qkv,
                                                   const float* __restrict__ rpb,
                                                   bf16* __restrict__ out)
{
    int win  = blockIdx.x / NHH;
    int head = blockIdx.x % NHH;
    int tid  = threadIdx.x;
    int lane = tid & 31, w = tid >> 5;

    __shared__ float sq[NN*33], sk[NN*33], sv[NN*33];
    __shared__ float sp[NN*50];
    __shared__ int   sgrp[NN];

    const bf16* base = qkv + (size_t)win*NN*(3*CC) + head*HD;
    for (int i = tid; i < NN*HD; i += 128) {
        int n = i >> 5, d = i & 31;
        sq[n*33+d] = __bfloat162float(base[(size_t)n*(3*CC) + d]);
        sk[n*33+d] = __bfloat162float(base[(size_t)n*(3*CC) + CC + d]);
        sv[n*33+d] = __bfloat162float(base[(size_t)n*(3*CC) + 2*CC + d]);
    }
    if (tid < NN) {
        int wi = win % NWIN;
        int wh = wi >> 3, ww = wi & 7;
        int r = tid / WS, c = tid % WS;
        int hh = wh*WS + r, wg = ww*WS + c;
        int gh = (hh < HH-WS) ? 0 : ((hh < HH-SHIFT) ? 1 : 2);
        int gw = (wg < WW_-WS) ? 0 : ((wg < WW_-SHIFT) ? 1 : 2);
        sgrp[tid] = gh*3 + gw;
    }
    __syncthreads();

    const float scale = 0.17677669529663687f;
    for (int i = w; i < NN; i += 4) {
        int ih = i / WS, iw = i % WS;
        int j1 = lane;
        int j2 = lane + 32;
        bool has2 = (j2 < NN);
        int j2c = has2 ? j2 : 0;
        float a1 = 0.f, a2 = 0.f;
        #pragma unroll
        for (int d = 0; d < HD; d++) {
            float qd = sq[i*33+d];
            a1 = fmaf(qd, sk[j1*33+d], a1);
            a2 = fmaf(qd, sk[j2c*33+d], a2);
        }
        int jh = j1 / WS, jw = j1 % WS;
        int ridx = (ih - jh + 6)*13 + (iw - jw + 6);
        float s1 = a1*scale + rpb[ridx*NHH + head] + ((sgrp[i] != sgrp[j1]) ? -100.f : 0.f);
        float s2 = -1e30f;
        if (has2) {
            jh = j2 / WS; jw = j2 % WS;
            ridx = (ih - jh + 6)*13 + (iw - jw + 6);
            s2 = a2*scale + rpb[ridx*NHH + head] + ((sgrp[i] != sgrp[j2]) ? -100.f : 0.f);
        }
        float m = warpMax(fmaxf(s1, s2));
        float e1 = __expf(s1 - m);
        float e2 = has2 ? __expf(s2 - m) : 0.f;
        float sum = warpSum(e1 + e2);
        float inv = 1.f / sum;
        sp[i*50 + j1] = e1 * inv;
        if (has2) sp[i*50 + j2] = e2 * inv;
    }
    __syncthreads();

    for (int i = w; i < NN; i += 4) {
        int d = lane;
        float acc = 0.f;
        #pragma unroll 7
        for (int j = 0; j < NN; j++)
            acc = fmaf(sp[i*50+j], sv[j*33+d], acc);
        out[((size_t)(win*NN + i))*CC + head*HD + d] = __float2bfloat16(acc);
    }
}

// ---------------- launch ----------------
extern "C" void kernel_launch(void* const* d_in, const int* in_sizes, int n_in,
                              void* d_out, int out_size)
{
    const float* x      = (const float*)d_in[0];
    const float* qkv_w  = (const float*)d_in[1];
    const float* qkv_b  = (const float*)d_in[2];
    const float* proj_w = (const float*)d_in[3];
    const float* proj_b = (const float*)d_in[4];
    const float* rpb    = (const float*)d_in[5];
    const float* n1g    = (const float*)d_in[6];
    const float* n1b    = (const float*)d_in[7];
    const float* n2g    = (const float*)d_in[8];
    const float* n2b    = (const float*)d_in[9];
    const float* w1     = (const float*)d_in[10];
    const float* b1     = (const float*)d_in[11];
    const float* w2     = (const float*)d_in[12];
    const float* b2     = (const float*)d_in[13];
    float* out = (float*)d_out;

    bf16 *p_ln1, *p_qkvb, *p_attnb, *p_ln2, *p_h1b, *p_wq, *p_wp, *p_w1, *p_w2;
    float *p_x1;
    cudaGetSymbolAddress((void**)&p_ln1,  g_ln1);
    cudaGetSymbolAddress((void**)&p_qkvb, g_qkvb);
    cudaGetSymbolAddress((void**)&p_attnb,g_attnb);
    cudaGetSymbolAddress((void**)&p_ln2,  g_ln2);
    cudaGetSymbolAddress((void**)&p_h1b,  g_h1b);
    cudaGetSymbolAddress((void**)&p_x1,   g_x1);
    cudaGetSymbolAddress((void**)&p_wq,   g_wq);
    cudaGetSymbolAddress((void**)&p_wp,   g_wp);
    cudaGetSymbolAddress((void**)&p_w1,   g_w1);
    cudaGetSymbolAddress((void**)&p_w2,   g_w2);

    // 0) weights -> bf16
    f2bf_kernel<<<(3*CC*CC + 255)/256, 256>>>(qkv_w, p_wq, 3*CC*CC);
    f2bf_kernel<<<(CC*CC   + 255)/256, 256>>>(proj_w, p_wp, CC*CC);
    f2bf_kernel<<<(HID*CC  + 255)/256, 256>>>(w1, p_w1, HID*CC);
    f2bf_kernel<<<(CC*HID  + 255)/256, 256>>>(w2, p_w2, CC*HID);

    // 1) LN1 + roll + window partition -> bf16
    ln_kernel<true><<<TOK, 192>>>(x, n1g, n1b, p_ln1);

    // 2) qkv GEMM (HMMA): (TOK x 192) @ (576 x 192)^T -> bf16
    mma_gemm<0><<<dim3(9, TOK/128), 256>>>(p_ln1, p_wq, qkv_b, nullptr, p_qkvb, 3*CC, CC);

    // 3) windowed attention -> bf16
    attn_kernel<<<BW*NHH, 128>>>(p_qkvb, rpb, p_attnb);

    // 4) proj GEMM + window reverse + roll back + residual -> g_x1 (fp32)
    mma_gemm<2><<<dim3(3, TOK/128), 256>>>(p_attnb, p_wp, proj_b, x, p_x1, CC, CC);

    // 5) LN2 -> bf16
    ln_kernel<false><<<TOK, 192>>>(p_x1, n2g, n2b, p_ln2);

    // 6) fc1 + gelu -> bf16
    mma_gemm<1><<<dim3(12, TOK/128), 256>>>(p_ln2, p_w1, b1, nullptr, p_h1b, HID, CC);

    // 7) fc2 + bias + residual -> d_out (fp32)
    mma_gemm<3><<<dim3(3, TOK/128), 256>>>(p_h1b, p_w2, b2, p_x1, out, CC, HID);
}

// round 8
// speedup vs baseline: 3.1874x; 1.3848x over previous
#include <cuda_runtime.h>
#include <cuda_bf16.h>
#include <math.h>
#include <stdint.h>

// ---------------- problem constants ----------------
#define BSZ   32
#define HH    56
#define WW_   56
#define CC    192
#define LL    (HH*WW_)          // 3136
#define WS    7
#define NN    49
#define NHH   6
#define HD    32
#define SHIFT 3
#define NWIN  64
#define BW    (BSZ*NWIN)        // 2048
#define TOK   (BW*NN)           // 100352
#define HID   768

typedef __nv_bfloat16 bf16;

// ---------------- scratch (static device, no allocs) ----------------
__device__ __align__(256) bf16 g_ln1 [(size_t)TOK*CC];
__device__ __align__(256) bf16 g_qkvb[(size_t)TOK*3*CC];
__device__ __align__(256) bf16 g_attnb[(size_t)TOK*CC];
__device__ __align__(256) bf16 g_ln2 [(size_t)TOK*CC];
__device__ __align__(256) bf16 g_h1b [(size_t)TOK*HID];
__device__ __align__(256) float g_x1 [(size_t)TOK*CC];
__device__ __align__(256) bf16 g_wq[3*CC*CC];
__device__ __align__(256) bf16 g_wp[CC*CC];
__device__ __align__(256) bf16 g_w1[HID*CC];
__device__ __align__(256) bf16 g_w2[CC*HID];

// ---------------- helpers ----------------
__device__ __forceinline__ float warpSum(float v){
    #pragma unroll
    for (int o=16;o;o>>=1) v += __shfl_xor_sync(0xffffffffu, v, o);
    return v;
}
__device__ __forceinline__ void mma_bf16(float* acc, uint32_t a0, uint32_t a1, uint32_t a2, uint32_t a3,
                                         uint32_t b0, uint32_t b1){
    asm volatile(
        "mma.sync.aligned.m16n8k16.row.col.f32.bf16.bf16.f32 "
        "{%0,%1,%2,%3}, {%4,%5,%6,%7}, {%8,%9}, {%0,%1,%2,%3};"
        : "+f"(acc[0]), "+f"(acc[1]), "+f"(acc[2]), "+f"(acc[3])
        : "r"(a0), "r"(a1), "r"(a2), "r"(a3), "r"(b0), "r"(b1));
}
__device__ __forceinline__ void cpa16(void* dst, const void* src){
    uint32_t d = (uint32_t)__cvta_generic_to_shared(dst);
    asm volatile("cp.async.cg.shared.global [%0], [%1], 16;" :: "r"(d), "l"(src));
}
__device__ __forceinline__ uint32_t packbf2(float a, float b){
    __nv_bfloat162 p = __floats2bfloat162_rn(a, b);
    return *(uint32_t*)&p;
}

static __device__ __forceinline__ size_t winrow_to_img(int m){
    int win = m / NN, n = m % NN;
    int b = win >> 6, wi = win & 63;
    int hr = (wi >> 3)*WS + n/WS;
    int wr = (wi & 7)*WS + n%WS;
    int h = hr + SHIFT; if (h >= HH) h -= HH;
    int w = wr + SHIFT; if (w >= WW_) w -= WW_;
    return (size_t)b*LL + (size_t)h*WW_ + w;
}

// ---------------- fp32 -> bf16 convert ----------------
__global__ void f2bf_kernel(const float* __restrict__ s, bf16* __restrict__ d, int n){
    int i = blockIdx.x*256 + threadIdx.x;
    if (i < n) d[i] = __float2bfloat16(s[i]);
}

// ---------------- LayerNorm (192 ch) -> bf16, optional roll+window gather ----------------
template<bool GATHER>
__global__ __launch_bounds__(192) void ln_kernel(const float* __restrict__ x,
                                                 const float* __restrict__ gamma,
                                                 const float* __restrict__ beta,
                                                 bf16* __restrict__ out)
{
    int t = blockIdx.x;
    int tid = threadIdx.x;
    size_t src = GATHER ? winrow_to_img(t) * CC + tid : (size_t)t * CC + tid;
    float v = x[src];

    __shared__ float red[8];
    int lane = tid & 31, wid = tid >> 5;
    float s = warpSum(v);
    if (lane == 0) red[wid] = s;
    __syncthreads();
    if (tid == 0) {
        float m = 0.f;
        #pragma unroll
        for (int i=0;i<6;i++) m += red[i];
        red[6] = m * (1.f/CC);
    }
    __syncthreads();
    float mean = red[6];
    float d = v - mean;
    s = warpSum(d*d);
    __syncthreads();
    if (lane == 0) red[wid] = s;
    __syncthreads();
    if (tid == 0) {
        float q = 0.f;
        #pragma unroll
        for (int i=0;i<6;i++) q += red[i];
        red[7] = rsqrtf(q * (1.f/CC) + 1e-5f);
    }
    __syncthreads();
    float rstd = red[7];
    out[(size_t)t*CC + tid] = __float2bfloat16(d * rstd * gamma[tid] + beta[tid]);
}

// ---------------- HMMA bf16 GEMM, cp.async 3-stage pipeline ----------------
// tile 128(M) x 64(N), BK=32, 256 threads, warp grid 4(M) x 2(N), warp tile 32x32.
// EPI 0: +bias -> bf16 | 1: +bias,gelu -> bf16 | 2: +bias +x[imgrow] -> fp32 | 3: +bias +xin -> fp32
#define LDA 40   // smem row stride in bf16 elems

template<int EPI, int N, int K>
__global__ __launch_bounds__(256) void mma_gemm(const bf16* __restrict__ A,
                                                const bf16* __restrict__ Wt,
                                                const float* __restrict__ bias,
                                                const float* __restrict__ xin,
                                                void* __restrict__ outp)
{
    constexpr int NITER = K / 32;
    __shared__ __align__(16) bf16 As[3][128*LDA];
    __shared__ __align__(16) bf16 Bs[3][64*LDA];

    int tid = threadIdx.x;
    int wid = tid >> 5, lane = tid & 31;
    int g = lane >> 2, t4 = lane & 3;
    int wm = (wid >> 1) * 32;
    int wn = (wid & 1) * 32;
    int mBase = blockIdx.y * 128;
    int nBase = blockIdx.x * 64;

    const bf16* Abase = A  + (size_t)mBase * K;
    const bf16* Bbase = Wt + (size_t)nBase * K;

    int lr  = tid >> 2;        // A load row helper (0..63)
    int lc8 = tid & 3;         // 16B chunk within 32-wide k

    auto loadTiles = [&](int kt, int s){
        #pragma unroll
        for (int i = 0; i < 2; i++) {
            int r = lr + i*64;
            cpa16(&As[s][r*LDA + lc8*8], Abase + (size_t)r*K + kt + lc8*8);
        }
        cpa16(&Bs[s][lr*LDA + lc8*8], Bbase + (size_t)lr*K + kt + lc8*8);
        asm volatile("cp.async.commit_group;" ::: "memory");
    };

    float acc[2][4][4];
    #pragma unroll
    for (int mi=0;mi<2;mi++)
        #pragma unroll
        for (int ni=0;ni<4;ni++)
            #pragma unroll
            for (int c=0;c<4;c++) acc[mi][ni][c] = 0.f;

    loadTiles(0, 0);
    loadTiles(32, 1);

    #pragma unroll
    for (int it = 0; it < NITER; it++) {
        if (it < NITER-1) asm volatile("cp.async.wait_group 1;" ::: "memory");
        else              asm volatile("cp.async.wait_group 0;" ::: "memory");
        __syncthreads();
        if (it + 2 < NITER) loadTiles((it+2)*32, (it+2)%3);

        const bf16* as = As[it%3];
        const bf16* bs = Bs[it%3];
        #pragma unroll
        for (int ks = 0; ks < 2; ks++) {
            uint32_t af[2][4], bfr[4][2];
            #pragma unroll
            for (int mi = 0; mi < 2; mi++) {
                int r0 = wm + mi*16 + g;
                af[mi][0] = *(const uint32_t*)&as[(r0  )*LDA + ks*16 + t4*2    ];
                af[mi][1] = *(const uint32_t*)&as[(r0+8)*LDA + ks*16 + t4*2    ];
                af[mi][2] = *(const uint32_t*)&as[(r0  )*LDA + ks*16 + t4*2 + 8];
                af[mi][3] = *(const uint32_t*)&as[(r0+8)*LDA + ks*16 + t4*2 + 8];
            }
            #pragma unroll
            for (int ni = 0; ni < 4; ni++) {
                int n0 = wn + ni*8 + g;
                bfr[ni][0] = *(const uint32_t*)&bs[n0*LDA + ks*16 + t4*2    ];
                bfr[ni][1] = *(const uint32_t*)&bs[n0*LDA + ks*16 + t4*2 + 8];
            }
            #pragma unroll
            for (int mi = 0; mi < 2; mi++)
                #pragma unroll
                for (int ni = 0; ni < 4; ni++)
                    mma_bf16(acc[mi][ni], af[mi][0], af[mi][1], af[mi][2], af[mi][3],
                             bfr[ni][0], bfr[ni][1]);
        }
        __syncthreads();
    }

    // ---------------- epilogue ----------------
    #pragma unroll
    for (int ni = 0; ni < 4; ni++) {
        int n = nBase + wn + ni*8 + t4*2;
        float b0v = __ldg(bias + n), b1v = __ldg(bias + n + 1);
        #pragma unroll
        for (int mi = 0; mi < 2; mi++) {
            #pragma unroll
            for (int h = 0; h < 2; h++) {
                int m = mBase + wm + mi*16 + h*8 + g;
                float u0 = acc[mi][ni][h*2+0] + b0v;
                float u1 = acc[mi][ni][h*2+1] + b1v;
                if (EPI == 1) {
                    float y0 = 0.7978845608028654f * (u0 + 0.044715f*u0*u0*u0);
                    float y1 = 0.7978845608028654f * (u1 + 0.044715f*u1*u1*u1);
                    float t0 = 1.f - 2.f/(__expf(2.f*y0)+1.f);
                    float t1 = 1.f - 2.f/(__expf(2.f*y1)+1.f);
                    u0 = 0.5f*u0*(1.f+t0);
                    u1 = 0.5f*u1*(1.f+t1);
                }
                if (EPI == 0 || EPI == 1) {
                    *(uint32_t*)((bf16*)outp + (size_t)m * N + n) = packbf2(u0, u1);
                } else {
                    size_t drow = (EPI == 2) ? winrow_to_img(m) : (size_t)m;
                    size_t o = drow * CC + n;
                    float2 xv = *(const float2*)(xin + o);
                    float2 ov; ov.x = u0 + xv.x; ov.y = u1 + xv.y;
                    *(float2*)((float*)outp + o) = ov;
                }
            }
        }
    }
}

// ---------------- HMMA windowed attention: one block per (window, head) ----------------
// Q/K padded to 64 rows in smem; V transposed [dim][token] padded to 64 k.
// bias table (rpb + shift mask + padding -inf) precomputed 64x64 in smem.
#define ALD 40
#define VLD 72

__global__ __launch_bounds__(128) void attn_mma(const bf16* __restrict__ qkv,
                                                const float* __restrict__ rpb,
                                                bf16* __restrict__ out)
{
    __shared__ __align__(16) bf16 sq[64*ALD];
    __shared__ __align__(16) bf16 sk[64*ALD];
    __shared__ __align__(16) bf16 sVt[32*VLD];
    __shared__ float sbias[64*64];
    __shared__ int   sgrp[64];

    int win  = blockIdx.x / NHH;
    int head = blockIdx.x % NHH;
    int tid  = threadIdx.x;
    int lane = tid & 31, w = tid >> 5;
    int g = lane >> 2, t4 = lane & 3;

    // zero all of sq/sk (covers padding rows) and sVt (covers padding cols)
    uint32_t* zq = (uint32_t*)sq;
    uint32_t* zk = (uint32_t*)sk;
    uint32_t* zv = (uint32_t*)sVt;
    #pragma unroll
    for (int i = 0; i < 10; i++) { zq[tid + i*128] = 0u; zk[tid + i*128] = 0u; }
    #pragma unroll
    for (int i = 0; i < 9; i++)  { zv[tid + i*128] = 0u; }
    if (tid < NN) {
        int wi = win & 63;
        int wh = wi >> 3, ww = wi & 7;
        int r = tid / WS, c = tid % WS;
        int hh = wh*WS + r, wg = ww*WS + c;
        int gh = (hh < HH-WS) ? 0 : ((hh < HH-SHIFT) ? 1 : 2);
        int gw = (wg < WW_-WS) ? 0 : ((wg < WW_-SHIFT) ? 1 : 2);
        sgrp[tid] = gh*3 + gw;
    }
    __syncthreads();

    // fill q (scaled), k, v^T
    const bf16* base = qkv + (size_t)win*NN*(3*CC) + head*HD;
    const float scale = 0.17677669529663687f;
    for (int i = tid; i < NN*HD; i += 128) {
        int n = i >> 5, d = i & 31;
        float qv = __bfloat162float(base[(size_t)n*(3*CC) + d]) * scale;
        sq[n*ALD + d]  = __float2bfloat16(qv);
        sk[n*ALD + d]  = base[(size_t)n*(3*CC) + CC + d];
        sVt[d*VLD + n] = base[(size_t)n*(3*CC) + 2*CC + d];
    }
    // bias table
    for (int i = tid; i < 64*64; i += 128) {
        int r = i >> 6, c = i & 63;
        float v;
        if (c >= NN) v = -1e9f;
        else if (r >= NN) v = 0.f;
        else {
            int ih = r / WS, iw = r % WS, jh = c / WS, jw = c % WS;
            v = rpb[((ih-jh+6)*13 + (iw-jw+6))*NHH + head]
              + ((sgrp[r] != sgrp[c]) ? -100.f : 0.f);
        }
        sbias[i] = v;
    }
    __syncthreads();

    // ---- S = Q K^T : warp w covers rows 16w..16w+15, cols 0..63 (8 n-tiles) ----
    float sa[8][4];
    #pragma unroll
    for (int nt = 0; nt < 8; nt++)
        #pragma unroll
        for (int c = 0; c < 4; c++) sa[nt][c] = 0.f;

    int r0 = w*16 + g;
    #pragma unroll
    for (int kt = 0; kt < 2; kt++) {
        uint32_t a0 = *(const uint32_t*)&sq[(r0  )*ALD + kt*16 + t4*2    ];
        uint32_t a1 = *(const uint32_t*)&sq[(r0+8)*ALD + kt*16 + t4*2    ];
        uint32_t a2 = *(const uint32_t*)&sq[(r0  )*ALD + kt*16 + t4*2 + 8];
        uint32_t a3 = *(const uint32_t*)&sq[(r0+8)*ALD + kt*16 + t4*2 + 8];
        #pragma unroll
        for (int nt = 0; nt < 8; nt++) {
            int n0 = nt*8 + g;
            uint32_t b0 = *(const uint32_t*)&sk[n0*ALD + kt*16 + t4*2    ];
            uint32_t b1 = *(const uint32_t*)&sk[n0*ALD + kt*16 + t4*2 + 8];
            mma_bf16(sa[nt], a0, a1, a2, a3, b0, b1);
        }
    }

    // ---- softmax (rows r0 and r0+8), all in registers + quad shuffles ----
    int rlo = r0, rhi = r0 + 8;
    float mlo = -1e30f, mhi = -1e30f;
    #pragma unroll
    for (int nt = 0; nt < 8; nt++) {
        float2 blo = *(const float2*)&sbias[rlo*64 + nt*8 + t4*2];
        float2 bhi = *(const float2*)&sbias[rhi*64 + nt*8 + t4*2];
        sa[nt][0] += blo.x; sa[nt][1] += blo.y;
        sa[nt][2] += bhi.x; sa[nt][3] += bhi.y;
        mlo = fmaxf(mlo, fmaxf(sa[nt][0], sa[nt][1]));
        mhi = fmaxf(mhi, fmaxf(sa[nt][2], sa[nt][3]));
    }
    mlo = fmaxf(mlo, __shfl_xor_sync(0xffffffffu, mlo, 1));
    mlo = fmaxf(mlo, __shfl_xor_sync(0xffffffffu, mlo, 2));
    mhi = fmaxf(mhi, __shfl_xor_sync(0xffffffffu, mhi, 1));
    mhi = fmaxf(mhi, __shfl_xor_sync(0xffffffffu, mhi, 2));
    float slo = 0.f, shi = 0.f;
    #pragma unroll
    for (int nt = 0; nt < 8; nt++) {
        sa[nt][0] = __expf(sa[nt][0] - mlo);
        sa[nt][1] = __expf(sa[nt][1] - mlo);
        sa[nt][2] = __expf(sa[nt][2] - mhi);
        sa[nt][3] = __expf(sa[nt][3] - mhi);
        slo += sa[nt][0] + sa[nt][1];
        shi += sa[nt][2] + sa[nt][3];
    }
    slo += __shfl_xor_sync(0xffffffffu, slo, 1);
    slo += __shfl_xor_sync(0xffffffffu, slo, 2);
    shi += __shfl_xor_sync(0xffffffffu, shi, 1);
    shi += __shfl_xor_sync(0xffffffffu, shi, 2);
    float ilo = 1.f / slo, ihi = 1.f / shi;

    uint32_t plo[8], phi[8];
    #pragma unroll
    for (int nt = 0; nt < 8; nt++) {
        plo[nt] = packbf2(sa[nt][0]*ilo, sa[nt][1]*ilo);
        phi[nt] = packbf2(sa[nt][2]*ihi, sa[nt][3]*ihi);
    }

    // ---- O = P V : k = 64 (4 k-tiles), n = 32 (4 n-tiles) ----
    float oacc[4][4];
    #pragma unroll
    for (int nt = 0; nt < 4; nt++)
        #pragma unroll
        for (int c = 0; c < 4; c++) oacc[nt][c] = 0.f;

    #pragma unroll
    for (int kt = 0; kt < 4; kt++) {
        uint32_t a0 = plo[2*kt], a1 = phi[2*kt], a2 = plo[2*kt+1], a3 = phi[2*kt+1];
        #pragma unroll
        for (int nt = 0; nt < 4; nt++) {
            int n0 = nt*8 + g;
            uint32_t b0 = *(const uint32_t*)&sVt[n0*VLD + kt*16 + t4*2    ];
            uint32_t b1 = *(const uint32_t*)&sVt[n0*VLD + kt*16 + t4*2 + 8];
            mma_bf16(oacc[nt], a0, a1, a2, a3, b0, b1);
        }
    }

    // ---- write out rows < 49, head-interleaved layout ----
    #pragma unroll
    for (int nt = 0; nt < 4; nt++) {
        int col = nt*8 + t4*2;
        if (rlo < NN)
            *(uint32_t*)(out + ((size_t)(win*NN + rlo))*CC + head*HD + col) =
                packbf2(oacc[nt][0], oacc[nt][1]);
        if (rhi < NN)
            *(uint32_t*)(out + ((size_t)(win*NN + rhi))*CC + head*HD + col) =
                packbf2(oacc[nt][2], oacc[nt][3]);
    }
}

// ---------------- launch ----------------
extern "C" void kernel_launch(void* const* d_in, const int* in_sizes, int n_in,
                              void* d_out, int out_size)
{
    const float* x      = (const float*)d_in[0];
    const float* qkv_w  = (const float*)d_in[1];
    const float* qkv_b  = (const float*)d_in[2];
    const float* proj_w = (const float*)d_in[3];
    const float* proj_b = (const float*)d_in[4];
    const float* rpb    = (const float*)d_in[5];
    const float* n1g    = (const float*)d_in[6];
    const float* n1b    = (const float*)d_in[7];
    const float* n2g    = (const float*)d_in[8];
    const float* n2b    = (const float*)d_in[9];
    const float* w1     = (const float*)d_in[10];
    const float* b1     = (const float*)d_in[11];
    const float* w2     = (const float*)d_in[12];
    const float* b2     = (const float*)d_in[13];
    float* out = (float*)d_out;

    bf16 *p_ln1, *p_qkvb, *p_attnb, *p_ln2, *p_h1b, *p_wq, *p_wp, *p_w1, *p_w2;
    float *p_x1;
    cudaGetSymbolAddress((void**)&p_ln1,  g_ln1);
    cudaGetSymbolAddress((void**)&p_qkvb, g_qkvb);
    cudaGetSymbolAddress((void**)&p_attnb,g_attnb);
    cudaGetSymbolAddress((void**)&p_ln2,  g_ln2);
    cudaGetSymbolAddress((void**)&p_h1b,  g_h1b);
    cudaGetSymbolAddress((void**)&p_x1,   g_x1);
    cudaGetSymbolAddress((void**)&p_wq,   g_wq);
    cudaGetSymbolAddress((void**)&p_wp,   g_wp);
    cudaGetSymbolAddress((void**)&p_w1,   g_w1);
    cudaGetSymbolAddress((void**)&p_w2,   g_w2);

    // 0) weights -> bf16
    f2bf_kernel<<<(3*CC*CC + 255)/256, 256>>>(qkv_w, p_wq, 3*CC*CC);
    f2bf_kernel<<<(CC*CC   + 255)/256, 256>>>(proj_w, p_wp, CC*CC);
    f2bf_kernel<<<(HID*CC  + 255)/256, 256>>>(w1, p_w1, HID*CC);
    f2bf_kernel<<<(CC*HID  + 255)/256, 256>>>(w2, p_w2, CC*HID);

    // 1) LN1 + roll + window partition -> bf16
    ln_kernel<true><<<TOK, 192>>>(x, n1g, n1b, p_ln1);

    // 2) qkv GEMM
    mma_gemm<0, 3*CC, CC><<<dim3(9, TOK/128), 256>>>(p_ln1, p_wq, qkv_b, nullptr, p_qkvb);

    // 3) windowed attention (HMMA)
    attn_mma<<<BW*NHH, 128>>>(p_qkvb, rpb, p_attnb);

    // 4) proj GEMM + window reverse + roll back + residual -> g_x1 (fp32)
    mma_gemm<2, CC, CC><<<dim3(3, TOK/128), 256>>>(p_attnb, p_wp, proj_b, x, p_x1);

    // 5) LN2 -> bf16
    ln_kernel<false><<<TOK, 192>>>(p_x1, n2g, n2b, p_ln2);

    // 6) fc1 + gelu -> bf16
    mma_gemm<1, HID, CC><<<dim3(12, TOK/128), 256>>>(p_ln2, p_w1, b1, nullptr, p_h1b);

    // 7) fc2 + bias + residual -> d_out (fp32)
    mma_gemm<3, CC, HID><<<dim3(3, TOK/128), 256>>>(p_h1b, p_w2, b2, p_x1, out);
}

// round 9
// speedup vs baseline: 4.1884x; 1.3140x over previous
#include <cuda_runtime.h>
#include <cuda_bf16.h>
#include <math.h>
#include <stdint.h>

// ---------------- problem constants ----------------
#define BSZ   32
#define HH    56
#define WW_   56
#define CC    192
#define LL    (HH*WW_)          // 3136
#define WS    7
#define NN    49
#define NHH   6
#define HD    32
#define SHIFT 3
#define NWIN  64
#define BW    (BSZ*NWIN)        // 2048
#define TOK   (BW*NN)           // 100352
#define HID   768

typedef __nv_bfloat16 bf16;

// ---------------- scratch (static device, no allocs) ----------------
__device__ __align__(256) bf16 g_ln1 [(size_t)TOK*CC];
__device__ __align__(256) bf16 g_qkvb[(size_t)TOK*3*CC];
__device__ __align__(256) bf16 g_attnb[(size_t)TOK*CC];
__device__ __align__(256) bf16 g_ln2 [(size_t)TOK*CC];
__device__ __align__(256) bf16 g_h1b [(size_t)TOK*HID];
__device__ __align__(256) float g_x1 [(size_t)TOK*CC];
__device__ __align__(256) bf16 g_wq[3*CC*CC];
__device__ __align__(256) bf16 g_wp[CC*CC];
__device__ __align__(256) bf16 g_w1[HID*CC];
__device__ __align__(256) bf16 g_w2[CC*HID];
__device__ __align__(256) float g_bias[4*NHH*64*64];   // precomputed bias+mask tables

// ---------------- helpers ----------------
__device__ __forceinline__ float warpSum(float v){
    #pragma unroll
    for (int o=16;o;o>>=1) v += __shfl_xor_sync(0xffffffffu, v, o);
    return v;
}
__device__ __forceinline__ void mma_bf16(float* acc, uint32_t a0, uint32_t a1, uint32_t a2, uint32_t a3,
                                         uint32_t b0, uint32_t b1){
    asm volatile(
        "mma.sync.aligned.m16n8k16.row.col.f32.bf16.bf16.f32 "
        "{%0,%1,%2,%3}, {%4,%5,%6,%7}, {%8,%9}, {%0,%1,%2,%3};"
        : "+f"(acc[0]), "+f"(acc[1]), "+f"(acc[2]), "+f"(acc[3])
        : "r"(a0), "r"(a1), "r"(a2), "r"(a3), "r"(b0), "r"(b1));
}
__device__ __forceinline__ void ldm4(uint32_t* r, const void* p){
    uint32_t a = (uint32_t)__cvta_generic_to_shared(p);
    asm volatile("ldmatrix.sync.aligned.m8n8.x4.shared.b16 {%0,%1,%2,%3}, [%4];"
                 : "=r"(r[0]), "=r"(r[1]), "=r"(r[2]), "=r"(r[3]) : "r"(a));
}
__device__ __forceinline__ void cpa16(void* dst, const void* src){
    uint32_t d = (uint32_t)__cvta_generic_to_shared(dst);
    asm volatile("cp.async.cg.shared.global [%0], [%1], 16;" :: "r"(d), "l"(src));
}
__device__ __forceinline__ uint32_t packbf2(float a, float b){
    __nv_bfloat162 p = __floats2bfloat162_rn(a, b);
    return *(uint32_t*)&p;
}

static __device__ __forceinline__ size_t winrow_to_img(int m){
    int win = m / NN, n = m % NN;
    int b = win >> 6, wi = win & 63;
    int hr = (wi >> 3)*WS + n/WS;
    int wr = (wi & 7)*WS + n%WS;
    int h = hr + SHIFT; if (h >= HH) h -= HH;
    int w = wr + SHIFT; if (w >= WW_) w -= WW_;
    return (size_t)b*LL + (size_t)h*WW_ + w;
}

// ---------------- fused fp32 -> bf16 weight convert ----------------
#define S0 (3*CC*CC)            // 110592
#define S1 (S0 + CC*CC)         // 147456
#define S2 (S1 + HID*CC)        // 294912
#define S3 (S2 + CC*HID)        // 442368
__global__ void f2bf4_kernel(const float* __restrict__ a, const float* __restrict__ b,
                             const float* __restrict__ c, const float* __restrict__ d,
                             bf16* __restrict__ oa, bf16* __restrict__ ob,
                             bf16* __restrict__ oc, bf16* __restrict__ od){
    int i = blockIdx.x*256 + threadIdx.x;
    if (i < S0)      oa[i]      = __float2bfloat16(a[i]);
    else if (i < S1) ob[i - S0] = __float2bfloat16(b[i - S0]);
    else if (i < S2) oc[i - S1] = __float2bfloat16(c[i - S1]);
    else if (i < S3) od[i - S2] = __float2bfloat16(d[i - S2]);
}

// ---------------- bias table precompute: 4 window types x 6 heads, 64x64 ----------------
__global__ __launch_bounds__(256) void bias_pre_kernel(const float* __restrict__ rpb,
                                                       float* __restrict__ bt)
{
    int wtype = blockIdx.x / NHH;
    int head  = blockIdx.x % NHH;
    int whE = wtype >> 1, wwE = wtype & 1;   // window at bottom / right edge
    float* o = bt + (size_t)blockIdx.x * 4096;
    for (int idx = threadIdx.x; idx < 4096; idx += 256) {
        int r = idx >> 6, c = idx & 63;
        float v;
        if (c >= NN) v = -1e9f;
        else if (r >= NN) v = 0.f;
        else {
            int ih = r / WS, iw = r % WS;
            int jh = c / WS, jw = c % WS;
            int grh = whE ? ((ih < 4) ? 1 : 2) : 0;
            int grw = wwE ? ((iw < 4) ? 1 : 2) : 0;
            int gch = whE ? ((jh < 4) ? 1 : 2) : 0;
            int gcw = wwE ? ((jw < 4) ? 1 : 2) : 0;
            v = rpb[((ih-jh+6)*13 + (iw-jw+6))*NHH + head]
              + (((grh*3+grw) != (gch*3+gcw)) ? -100.f : 0.f);
        }
        o[idx] = v;
    }
}

// ---------------- LayerNorm: warp per row, single pass ----------------
template<bool GATHER>
__global__ __launch_bounds__(256) void ln_kernel(const float* __restrict__ x,
                                                 const float* __restrict__ gamma,
                                                 const float* __restrict__ beta,
                                                 bf16* __restrict__ out)
{
    int w = threadIdx.x >> 5, lane = threadIdx.x & 31;
    int t = blockIdx.x*8 + w;
    size_t src = GATHER ? winrow_to_img(t) * CC : (size_t)t * CC;
    float v[6];
    #pragma unroll
    for (int i = 0; i < 6; i++) v[i] = x[src + lane + i*32];
    float s = 0.f, q = 0.f;
    #pragma unroll
    for (int i = 0; i < 6; i++) { s += v[i]; q = fmaf(v[i], v[i], q); }
    s = warpSum(s); q = warpSum(q);
    float mean = s * (1.f/CC);
    float rstd = rsqrtf(q * (1.f/CC) - mean*mean + 1e-5f);
    size_t dst = (size_t)t * CC;
    #pragma unroll
    for (int i = 0; i < 6; i++) {
        int ch = lane + i*32;
        out[dst + ch] = __float2bfloat16((v[i] - mean) * rstd * __ldg(gamma+ch) + __ldg(beta+ch));
    }
}

// ---------------- HMMA bf16 GEMM, 128x96 tile, ldmatrix, 3-stage cp.async ----------------
// 256 threads, warp grid 4(M) x 2(N), warp tile 32x48.
// EPI 0: +bias -> bf16 | 1: +bias,gelu -> bf16 | 2: +bias +x[imgrow] -> fp32 | 3: +bias +xin -> fp32
#define LDA 40
#define GEMM_SMEM ((3*128*LDA + 3*96*LDA)*2)   // 53760 bytes

template<int EPI, int N, int K>
__global__ __launch_bounds__(256) void mma_gemm(const bf16* __restrict__ A,
                                                const bf16* __restrict__ Wt,
                                                const float* __restrict__ bias,
                                                const float* __restrict__ xin,
                                                void* __restrict__ outp)
{
    constexpr int NITER = K / 32;
    extern __shared__ __align__(16) bf16 smem[];
    bf16* AsB = smem;                 // 3 stages of 128*LDA
    bf16* BsB = smem + 3*128*LDA;     // 3 stages of 96*LDA

    int tid = threadIdx.x;
    int wid = tid >> 5, lane = tid & 31;
    int g = lane >> 2, t4 = lane & 3;
    int wm = (wid >> 1) * 32;         // 4 warps in M
    int wn = (wid & 1) * 48;          // 2 warps in N
    int mBase = blockIdx.y * 128;
    int nBase = blockIdx.x * 96;

    const bf16* Abase = A  + (size_t)mBase * K;
    const bf16* Bbase = Wt + (size_t)nBase * K;

    int lrA  = tid >> 2;       // 0..63
    int lc8A = tid & 3;
    int lrB  = tid >> 1;       // 0..127 (use <96 rows via tid<192)
    int lc8B = (tid & 1) * 2;

    auto loadTiles = [&](int kt, int s){
        bf16* as = AsB + s*128*LDA;
        bf16* bs = BsB + s*96*LDA;
        #pragma unroll
        for (int i = 0; i < 2; i++) {
            int r = lrA + i*64;
            cpa16(&as[r*LDA + lc8A*8], Abase + (size_t)r*K + kt + lc8A*8);
        }
        if (tid < 192) {
            cpa16(&bs[lrB*LDA + lc8B*8],     Bbase + (size_t)lrB*K + kt + lc8B*8);
            cpa16(&bs[lrB*LDA + lc8B*8 + 8], Bbase + (size_t)lrB*K + kt + lc8B*8 + 8);
        }
        asm volatile("cp.async.commit_group;" ::: "memory");
    };

    float acc[2][6][4];
    #pragma unroll
    for (int mi=0;mi<2;mi++)
        #pragma unroll
        for (int ni=0;ni<6;ni++)
            #pragma unroll
            for (int c=0;c<4;c++) acc[mi][ni][c] = 0.f;

    // ldmatrix lane address components
    int aRowOff = ((lane>>3)&1)*8 + (lane&7);   // + mi*16 + wm
    int aColOff = ((lane>>4)&1)*8;              // + ks*16
    int bRowOff = ((lane>>4)&1)*8 + (lane&7);   // + p*16 + wn
    int bColOff = ((lane>>3)&1)*8;              // + ks*16

    loadTiles(0, 0);
    if (NITER > 1) loadTiles(32, 1);

    #pragma unroll
    for (int it = 0; it < NITER; it++) {
        if (it + 1 < NITER) asm volatile("cp.async.wait_group 1;" ::: "memory");
        else                asm volatile("cp.async.wait_group 0;" ::: "memory");
        __syncthreads();
        if (it + 2 < NITER) loadTiles((it+2)*32, (it+2)%3);

        const bf16* as = AsB + (it%3)*128*LDA;
        const bf16* bs = BsB + (it%3)*96*LDA;
        #pragma unroll
        for (int ks = 0; ks < 2; ks++) {
            uint32_t af[2][4], bfr[3][4];
            #pragma unroll
            for (int mi = 0; mi < 2; mi++)
                ldm4(af[mi], &as[(wm + mi*16 + aRowOff)*LDA + ks*16 + aColOff]);
            #pragma unroll
            for (int p = 0; p < 3; p++)
                ldm4(bfr[p], &bs[(wn + p*16 + bRowOff)*LDA + ks*16 + bColOff]);
            #pragma unroll
            for (int mi = 0; mi < 2; mi++)
                #pragma unroll
                for (int p = 0; p < 3; p++) {
                    mma_bf16(acc[mi][2*p  ], af[mi][0], af[mi][1], af[mi][2], af[mi][3],
                             bfr[p][0], bfr[p][1]);
                    mma_bf16(acc[mi][2*p+1], af[mi][0], af[mi][1], af[mi][2], af[mi][3],
                             bfr[p][2], bfr[p][3]);
                }
        }
        __syncthreads();
    }

    // ---------------- epilogue ----------------
    #pragma unroll
    for (int ni = 0; ni < 6; ni++) {
        int n = nBase + wn + ni*8 + t4*2;
        float b0v = __ldg(bias + n), b1v = __ldg(bias + n + 1);
        #pragma unroll
        for (int mi = 0; mi < 2; mi++) {
            #pragma unroll
            for (int h = 0; h < 2; h++) {
                int m = mBase + wm + mi*16 + h*8 + g;
                float u0 = acc[mi][ni][h*2+0] + b0v;
                float u1 = acc[mi][ni][h*2+1] + b1v;
                if (EPI == 1) {
                    float y0 = 0.7978845608028654f * (u0 + 0.044715f*u0*u0*u0);
                    float y1 = 0.7978845608028654f * (u1 + 0.044715f*u1*u1*u1);
                    float t0 = 1.f - 2.f/(__expf(2.f*y0)+1.f);
                    float t1 = 1.f - 2.f/(__expf(2.f*y1)+1.f);
                    u0 = 0.5f*u0*(1.f+t0);
                    u1 = 0.5f*u1*(1.f+t1);
                }
                if (EPI == 0 || EPI == 1) {
                    *(uint32_t*)((bf16*)outp + (size_t)m * N + n) = packbf2(u0, u1);
                } else {
                    size_t drow = (EPI == 2) ? winrow_to_img(m) : (size_t)m;
                    size_t o = drow * CC + n;
                    float2 xv = *(const float2*)(xin + o);
                    float2 ov; ov.x = u0 + xv.x; ov.y = u1 + xv.y;
                    *(float2*)((float*)outp + o) = ov;
                }
            }
        }
    }
}

// ---------------- HMMA windowed attention: one block per (window, head) ----------------
#define ALD 40
#define VLD 72

__global__ __launch_bounds__(128) void attn_mma(const bf16* __restrict__ qkv,
                                                const float* __restrict__ btab,
                                                bf16* __restrict__ out)
{
    __shared__ __align__(16) bf16 sq[64*ALD];
    __shared__ __align__(16) bf16 sk[64*ALD];
    __shared__ __align__(16) bf16 sVt[32*VLD];
    __shared__ __align__(16) float sbias[64*64];

    int win  = blockIdx.x / NHH;
    int head = blockIdx.x % NHH;
    int tid  = threadIdx.x;
    int lane = tid & 31, w = tid >> 5;
    int g = lane >> 2, t4 = lane & 3;

    int wi = win & 63;
    int wtype = (((wi>>3) == 7) ? 2 : 0) + (((wi&7) == 7) ? 1 : 0);
    const float* bt = btab + ((size_t)(wtype*NHH + head))*4096;
    #pragma unroll
    for (int i = 0; i < 8; i++)
        cpa16(&sbias[(tid + i*128)*4], bt + (tid + i*128)*4);
    asm volatile("cp.async.commit_group;" ::: "memory");

    // zero padding regions of q/k/v
    uint32_t* zq = (uint32_t*)sq;
    uint32_t* zk = (uint32_t*)sk;
    uint32_t* zv = (uint32_t*)sVt;
    #pragma unroll
    for (int i = 0; i < 10; i++) { zq[tid + i*128] = 0u; zk[tid + i*128] = 0u; }
    #pragma unroll
    for (int i = 0; i < 9; i++)  { zv[tid + i*128] = 0u; }
    __syncthreads();

    // fill q (scaled), k, v^T
    const bf16* base = qkv + (size_t)win*NN*(3*CC) + head*HD;
    const float scale = 0.17677669529663687f;
    for (int i = tid; i < NN*HD; i += 128) {
        int n = i >> 5, d = i & 31;
        float qv = __bfloat162float(base[(size_t)n*(3*CC) + d]) * scale;
        sq[n*ALD + d]  = __float2bfloat16(qv);
        sk[n*ALD + d]  = base[(size_t)n*(3*CC) + CC + d];
        sVt[d*VLD + n] = base[(size_t)n*(3*CC) + 2*CC + d];
    }
    asm volatile("cp.async.wait_group 0;" ::: "memory");
    __syncthreads();

    // ---- S = Q K^T : warp w rows 16w..16w+15, cols 0..63 ----
    float sa[8][4];
    #pragma unroll
    for (int nt = 0; nt < 8; nt++)
        #pragma unroll
        for (int c = 0; c < 4; c++) sa[nt][c] = 0.f;

    int r0 = w*16 + g;
    #pragma unroll
    for (int kt = 0; kt < 2; kt++) {
        uint32_t a0 = *(const uint32_t*)&sq[(r0  )*ALD + kt*16 + t4*2    ];
        uint32_t a1 = *(const uint32_t*)&sq[(r0+8)*ALD + kt*16 + t4*2    ];
        uint32_t a2 = *(const uint32_t*)&sq[(r0  )*ALD + kt*16 + t4*2 + 8];
        uint32_t a3 = *(const uint32_t*)&sq[(r0+8)*ALD + kt*16 + t4*2 + 8];
        #pragma unroll
        for (int nt = 0; nt < 8; nt++) {
            int n0 = nt*8 + g;
            uint32_t b0 = *(const uint32_t*)&sk[n0*ALD + kt*16 + t4*2    ];
            uint32_t b1 = *(const uint32_t*)&sk[n0*ALD + kt*16 + t4*2 + 8];
            mma_bf16(sa[nt], a0, a1, a2, a3, b0, b1);
        }
    }

    // ---- softmax in registers + quad shuffles ----
    int rlo = r0, rhi = r0 + 8;
    float mlo = -1e30f, mhi = -1e30f;
    #pragma unroll
    for (int nt = 0; nt < 8; nt++) {
        float2 blo = *(const float2*)&sbias[rlo*64 + nt*8 + t4*2];
        float2 bhi = *(const float2*)&sbias[rhi*64 + nt*8 + t4*2];
        sa[nt][0] += blo.x; sa[nt][1] += blo.y;
        sa[nt][2] += bhi.x; sa[nt][3] += bhi.y;
        mlo = fmaxf(mlo, fmaxf(sa[nt][0], sa[nt][1]));
        mhi = fmaxf(mhi, fmaxf(sa[nt][2], sa[nt][3]));
    }
    mlo = fmaxf(mlo, __shfl_xor_sync(0xffffffffu, mlo, 1));
    mlo = fmaxf(mlo, __shfl_xor_sync(0xffffffffu, mlo, 2));
    mhi = fmaxf(mhi, __shfl_xor_sync(0xffffffffu, mhi, 1));
    mhi = fmaxf(mhi, __shfl_xor_sync(0xffffffffu, mhi, 2));
    float slo = 0.f, shi = 0.f;
    #pragma unroll
    for (int nt = 0; nt < 8; nt++) {
        sa[nt][0] = __expf(sa[nt][0] - mlo);
        sa[nt][1] = __expf(sa[nt][1] - mlo);
        sa[nt][2] = __expf(sa[nt][2] - mhi);
        sa[nt][3] = __expf(sa[nt][3] - mhi);
        slo += sa[nt][0] + sa[nt][1];
        shi += sa[nt][2] + sa[nt][3];
    }
    slo += __shfl_xor_sync(0xffffffffu, slo, 1);
    slo += __shfl_xor_sync(0xffffffffu, slo, 2);
    shi += __shfl_xor_sync(0xffffffffu, shi, 1);
    shi += __shfl_xor_sync(0xffffffffu, shi, 2);
    float ilo = 1.f / slo, ihi = 1.f / shi;

    uint32_t plo[8], phi[8];
    #pragma unroll
    for (int nt = 0; nt < 8; nt++) {
        plo[nt] = packbf2(sa[nt][0]*ilo, sa[nt][1]*ilo);
        phi[nt] = packbf2(sa[nt][2]*ihi, sa[nt][3]*ihi);
    }

    // ---- O = P V ----
    float oacc[4][4];
    #pragma unroll
    for (int nt = 0; nt < 4; nt++)
        #pragma unroll
        for (int c = 0; c < 4; c++) oacc[nt][c] = 0.f;

    #pragma unroll
    for (int kt = 0; kt < 4; kt++) {
        uint32_t a0 = plo[2*kt], a1 = phi[2*kt], a2 = plo[2*kt+1], a3 = phi[2*kt+1];
        #pragma unroll
        for (int nt = 0; nt < 4; nt++) {
            int n0 = nt*8 + g;
            uint32_t b0 = *(const uint32_t*)&sVt[n0*VLD + kt*16 + t4*2    ];
            uint32_t b1 = *(const uint32_t*)&sVt[n0*VLD + kt*16 + t4*2 + 8];
            mma_bf16(oacc[nt], a0, a1, a2, a3, b0, b1);
        }
    }

    // ---- write out rows < 49 ----
    #pragma unroll
    for (int nt = 0; nt < 4; nt++) {
        int col = nt*8 + t4*2;
        if (rlo < NN)
            *(uint32_t*)(out + ((size_t)(win*NN + rlo))*CC + head*HD + col) =
                packbf2(oacc[nt][0], oacc[nt][1]);
        if (rhi < NN)
            *(uint32_t*)(out + ((size_t)(win*NN + rhi))*CC + head*HD + col) =
                packbf2(oacc[nt][2], oacc[nt][3]);
    }
}

// ---------------- launch ----------------
extern "C" void kernel_launch(void* const* d_in, const int* in_sizes, int n_in,
                              void* d_out, int out_size)
{
    const float* x      = (const float*)d_in[0];
    const float* qkv_w  = (const float*)d_in[1];
    const float* qkv_b  = (const float*)d_in[2];
    const float* proj_w = (const float*)d_in[3];
    const float* proj_b = (const float*)d_in[4];
    const float* rpb    = (const float*)d_in[5];
    const float* n1g    = (const float*)d_in[6];
    const float* n1b    = (const float*)d_in[7];
    const float* n2g    = (const float*)d_in[8];
    const float* n2b    = (const float*)d_in[9];
    const float* w1     = (const float*)d_in[10];
    const float* b1     = (const float*)d_in[11];
    const float* w2     = (const float*)d_in[12];
    const float* b2     = (const float*)d_in[13];
    float* out = (float*)d_out;

    bf16 *p_ln1, *p_qkvb, *p_attnb, *p_ln2, *p_h1b, *p_wq, *p_wp, *p_w1, *p_w2;
    float *p_x1, *p_bias;
    cudaGetSymbolAddress((void**)&p_ln1,  g_ln1);
    cudaGetSymbolAddress((void**)&p_qkvb, g_qkvb);
    cudaGetSymbolAddress((void**)&p_attnb,g_attnb);
    cudaGetSymbolAddress((void**)&p_ln2,  g_ln2);
    cudaGetSymbolAddress((void**)&p_h1b,  g_h1b);
    cudaGetSymbolAddress((void**)&p_x1,   g_x1);
    cudaGetSymbolAddress((void**)&p_wq,   g_wq);
    cudaGetSymbolAddress((void**)&p_wp,   g_wp);
    cudaGetSymbolAddress((void**)&p_w1,   g_w1);
    cudaGetSymbolAddress((void**)&p_w2,   g_w2);
    cudaGetSymbolAddress((void**)&p_bias, g_bias);

    cudaFuncSetAttribute(mma_gemm<0, 3*CC, CC>, cudaFuncAttributeMaxDynamicSharedMemorySize, GEMM_SMEM);
    cudaFuncSetAttribute(mma_gemm<2, CC, CC>,   cudaFuncAttributeMaxDynamicSharedMemorySize, GEMM_SMEM);
    cudaFuncSetAttribute(mma_gemm<1, HID, CC>,  cudaFuncAttributeMaxDynamicSharedMemorySize, GEMM_SMEM);
    cudaFuncSetAttribute(mma_gemm<3, CC, HID>,  cudaFuncAttributeMaxDynamicSharedMemorySize, GEMM_SMEM);

    // 0) weights -> bf16 (single kernel) + bias tables
    f2bf4_kernel<<<(S3 + 255)/256, 256>>>(qkv_w, proj_w, w1, w2, p_wq, p_wp, p_w1, p_w2);
    bias_pre_kernel<<<4*NHH, 256>>>(rpb, p_bias);

    // 1) LN1 + roll + window partition -> bf16
    ln_kernel<true><<<TOK/8, 256>>>(x, n1g, n1b, p_ln1);

    // 2) qkv GEMM
    mma_gemm<0, 3*CC, CC><<<dim3(6, TOK/128), 256, GEMM_SMEM>>>(p_ln1, p_wq, qkv_b, nullptr, p_qkvb);

    // 3) windowed attention (HMMA)
    attn_mma<<<BW*NHH, 128>>>(p_qkvb, p_bias, p_attnb);

    // 4) proj GEMM + window reverse + roll back + residual -> g_x1 (fp32)
    mma_gemm<2, CC, CC><<<dim3(2, TOK/128), 256, GEMM_SMEM>>>(p_attnb, p_wp, proj_b, x, p_x1);

    // 5) LN2 -> bf16
    ln_kernel<false><<<TOK/8, 256>>>(p_x1, n2g, n2b, p_ln2);

    // 6) fc1 + gelu -> bf16
    mma_gemm<1, HID, CC><<<dim3(8, TOK/128), 256, GEMM_SMEM>>>(p_ln2, p_w1, b1, nullptr, p_h1b);

    // 7) fc2 + bias + residual -> d_out (fp32)
    mma_gemm<3, CC, HID><<<dim3(2, TOK/128), 256, GEMM_SMEM>>>(p_h1b, p_w2, b2, p_x1, out);
}